// round 5
// baseline (speedup 1.0000x reference)
#include <cuda_runtime.h>

// OrbitalSpectralConv: B=8, C=128, H=W=128; kept modes: 32 kx rows x 17 ky cols.
// kx rows: mk 0..16 -> kx = mk; mk 17..31 -> kx = mk+96 == -(32-mk) mod 128.
#define NKY   17
#define NMK   32
#define NMODE 544           // 32*17
#define NSLICE 1024         // B*C

// Scratch (allocation banned -> device globals). 4.46 MB each.
__device__ float2 g_Xf[NSLICE * NMODE];
__device__ float2 g_Y [NSLICE * NMODE];

// ===========================================================================
// Kernel 1: forward partial DFT per (b,c) slice, with even/odd folding.
//   Phase 1 (w-DFT): G[h][ky] = Sp[h][0] + (-1)^ky Sp[h][64]
//                    + sum_{w=1..63} Sp[h][w] cos(t ky w) - i Sm[h][w] sin(t ky w)
//       Sp[w] = x[w]+x[128-w], Sm[w] = x[w]-x[128-w],  t = 2pi/128
//   Phase 2 (h-DFT): fold h and share trig between +a and -a kx modes:
//       C1 = sum cos(ah) Gp_re, C2 = sum cos(ah) Gp_im,
//       S1 = sum sin(ah) Gm_re, S2 = sum sin(ah) Gm_im
//       Xf[+a] = (C1+S2, C2-S1),  Xf[-a] = (C1-S2, C2+S1)
// ===========================================================================
__global__ __launch_bounds__(320) void k_fwd(const float* __restrict__ X) {
    extern __shared__ char smem_raw[];
    float2* T1 = (float2*)smem_raw;        // [64][18] trig rows (padded for float4)
    float2* Gs = T1 + 64 * 18;             // [128][17]
    float2* tb = Gs + 128 * 17;            // [128]
    float*  Sp = (float*)(tb + 128);       // [128][65]
    float*  Sm = Sp + 128 * 65;            // [128][65]

    const int tid = threadIdx.x;

    if (tid < 128) {
        float s, c;
        sincospif((float)tid * (2.0f / 128.0f), &s, &c);
        tb[tid] = make_float2(c, s);
    }
    __syncthreads();

    // per-w trig rows: T1[w][ky] = (cos, sin)(2pi*ky*w/128)
    for (int i = tid; i < 64 * NKY; i += 320) {
        int w = i / NKY, ky = i - w * NKY;
        T1[w * 18 + ky] = tb[(w * ky) & 127];
    }

    // Stage A: fold X rows into Sp/Sm
    const float* Xp = X + (size_t)blockIdx.x * 16384;
    for (int i = tid; i < 128 * 64; i += 320) {
        int h = i >> 6, w = i & 63;
        float xa = Xp[h * 128 + w];
        if (w == 0) {
            Sp[h * 65 + 0]  = xa;
            Sp[h * 65 + 64] = Xp[h * 128 + 64];
        } else {
            float xb = Xp[h * 128 + 128 - w];
            Sp[h * 65 + w] = xa + xb;
            Sm[h * 65 + w] = xa - xb;
        }
    }
    __syncthreads();

    // Phase 1: 256 threads, thread = (h, ky-half). half0: ky 0..8, half1: ky 8..16.
    if (tid < 256) {
        const int h  = tid & 127;
        const int kb = (tid >> 7) * 8;
        float gre[9], gim[9];
        float s0 = Sp[h * 65 + 0], s64 = Sp[h * 65 + 64];
        #pragma unroll
        for (int j = 0; j < 9; j++) {
            gre[j] = s0 + (((kb + j) & 1) ? -s64 : s64);
            gim[j] = 0.f;
        }
        #pragma unroll 7
        for (int w = 1; w < 64; w++) {
            float sp  = Sp[h * 65 + w];
            float nsm = -Sm[h * 65 + w];
            const float4* tp = (const float4*)(T1 + w * 18 + kb);
            float4 tA = tp[0];
            float4 tB = tp[1];
            float4 tC = tp[2];
            float4 tD = tp[3];
            float2 tE = *(const float2*)(T1 + w * 18 + kb + 8);
            gre[0] = fmaf(tA.x, sp, gre[0]);  gim[0] = fmaf(tA.y, nsm, gim[0]);
            gre[1] = fmaf(tA.z, sp, gre[1]);  gim[1] = fmaf(tA.w, nsm, gim[1]);
            gre[2] = fmaf(tB.x, sp, gre[2]);  gim[2] = fmaf(tB.y, nsm, gim[2]);
            gre[3] = fmaf(tB.z, sp, gre[3]);  gim[3] = fmaf(tB.w, nsm, gim[3]);
            gre[4] = fmaf(tC.x, sp, gre[4]);  gim[4] = fmaf(tC.y, nsm, gim[4]);
            gre[5] = fmaf(tC.z, sp, gre[5]);  gim[5] = fmaf(tC.w, nsm, gim[5]);
            gre[6] = fmaf(tD.x, sp, gre[6]);  gim[6] = fmaf(tD.y, nsm, gim[6]);
            gre[7] = fmaf(tD.z, sp, gre[7]);  gim[7] = fmaf(tD.w, nsm, gim[7]);
            gre[8] = fmaf(tE.x, sp, gre[8]);  gim[8] = fmaf(tE.y, nsm, gim[8]);
        }
        #pragma unroll
        for (int j = 0; j < 9; j++)
            Gs[h * 17 + kb + j] = make_float2(gre[j], gim[j]);
    }
    __syncthreads();

    // Phase 2: 289 items (a=0..16, ky=0..16), each emits Xf[+a] and Xf[-a].
    float2* Xfp = g_Xf + (size_t)blockIdx.x * NMODE;
    const float inv = 1.0f / 16384.0f;
    for (int i = tid; i < 17 * NKY; i += 320) {
        int a = i / NKY, ky = i - a * NKY;
        float2 g0  = Gs[0 * 17 + ky];
        float2 g64 = Gs[64 * 17 + ky];
        float sgn = (a & 1) ? -1.f : 1.f;
        float C1 = g0.x + sgn * g64.x;
        float C2 = g0.y + sgn * g64.y;
        float S1 = 0.f, S2 = 0.f;
        int p = a;
        for (int h = 1; h < 64; h++) {
            float2 t  = tb[p & 127];
            float2 ga = Gs[h * 17 + ky];
            float2 gb = Gs[(128 - h) * 17 + ky];
            float pr = ga.x + gb.x, pi = ga.y + gb.y;
            float mr = ga.x - gb.x, mi = ga.y - gb.y;
            C1 = fmaf(t.x, pr, C1);
            C2 = fmaf(t.x, pi, C2);
            S1 = fmaf(t.y, mr, S1);
            S2 = fmaf(t.y, mi, S2);
            p += a;
        }
        Xfp[a * NKY + ky] = make_float2((C1 + S2) * inv, (C2 - S1) * inv);
        if (a >= 1 && a <= 15)
            Xfp[(32 - a) * NKY + ky] = make_float2((C1 - S2) * inv, (C2 + S1) * inv);
    }
}

// ===========================================================================
// Kernel 2: spectral channel mix, skew-Hermitian weight built on the fly.
//   Y[b,c,m] = sum_ct [(re[c,ct,m]-re[ct,c,m]) + i(im[c,ct,m]+im[ct,c,m])] Xf[b,ct,m]
// grid = 32 c-groups (4 c each) x 4 m-quarters; block = 272 = 136 m x 2 b-halves.
// Each thread: 4 c x 4 b complex accumulators.
// ===========================================================================
__global__ __launch_bounds__(272) void k_mix(const float* __restrict__ re,
                                             const float* __restrict__ im) {
    const int g   = blockIdx.x >> 2;
    const int mq  = blockIdx.x & 3;
    const int tid = threadIdx.x;
    const int mi  = tid % 136;
    const int bh  = tid / 136;          // 0 or 1
    const int m   = mq * 136 + mi;
    const int c0  = g * 4;

    float yr[4][4], yi[4][4];
    #pragma unroll
    for (int cc = 0; cc < 4; cc++)
        #pragma unroll
        for (int b = 0; b < 4; b++) { yr[cc][b] = 0.f; yi[cc][b] = 0.f; }

    const int base_c0 = c0 * 128 * NMODE + m;   // [c0][0][m]
    const int base_0c = c0 * NMODE + m;         // [0][c0][m]

    #pragma unroll 2
    for (int ct = 0; ct < 128; ct++) {
        const int offA = base_c0 + ct * NMODE;        // [c0+cc][ct][m] (+cc*128*NMODE)
        const int offB = base_0c + ct * 128 * NMODE;  // [ct][c0+cc][m] (+cc*NMODE)
        float wre[4], wim[4];
        #pragma unroll
        for (int cc = 0; cc < 4; cc++) {
            wre[cc] = re[offA + cc * 128 * NMODE] - re[offB + cc * NMODE];
            wim[cc] = im[offA + cc * 128 * NMODE] + im[offB + cc * NMODE];
        }
        const float2* xp = g_Xf + (bh * 4 * 128 + ct) * NMODE + m;
        #pragma unroll
        for (int b = 0; b < 4; b++) {
            float2 x = xp[b * 128 * NMODE];
            #pragma unroll
            for (int cc = 0; cc < 4; cc++) {
                yr[cc][b] = fmaf(wre[cc], x.x, fmaf(-wim[cc], x.y, yr[cc][b]));
                yi[cc][b] = fmaf(wre[cc], x.y, fmaf( wim[cc], x.x, yi[cc][b]));
            }
        }
    }
    #pragma unroll
    for (int cc = 0; cc < 4; cc++)
        #pragma unroll
        for (int b = 0; b < 4; b++)
            g_Y[((bh * 4 + b) * 128 + c0 + cc) * NMODE + m] =
                make_float2(yr[cc][b], yi[cc][b]);
}

// ===========================================================================
// Kernel 3: inverse per (b,c) slice, folded.
//   Phase A (kx->h): P[a]=Y[+a]+Y[-a], M[a]=Y[+a]-Y[-a];
//     C1..S2 as 4 sums over a=0..16; Z[h]=(C1-S2, C2+S1), Z[128-h]=(C1+S2, C2-S1)
//   Phase B (ky->w): C = sum a_ky Zre cos(t ky w), S = sum a_ky Zim sin(t ky w)
//     out[h][w] = C - S, out[h][128-w] = C + S.  a_0=1, a_{1..16}=2.
//     (c2r ignores Im(Z[.,0]) -> handled since sin(0)=0.)
// ===========================================================================
__global__ __launch_bounds__(320) void k_inv(float* __restrict__ out) {
    __shared__ float2 tb[128];
    __shared__ float2 Pa[NKY][NKY];     // [a][ky]
    __shared__ float2 Ma[NKY][NKY];
    __shared__ float2 Zs[128][18];      // padded for float4 row loads

    const int tid = threadIdx.x;
    if (tid < 128) {
        float s, c;
        sincospif((float)tid * (2.0f / 128.0f), &s, &c);
        tb[tid] = make_float2(c, s);
    }

    const float2* Yp = g_Y + (size_t)blockIdx.x * NMODE;
    for (int i = tid; i < 17 * NKY; i += 320) {
        int a = i / NKY, ky = i - a * NKY;
        float2 yp = Yp[a * NKY + ky];
        float2 P, M;
        if (a == 0)       { P = yp; M = make_float2(0.f, 0.f); }
        else if (a == 16) { P = yp; M = yp; }
        else {
            float2 yn = Yp[(32 - a) * NKY + ky];
            P = make_float2(yp.x + yn.x, yp.y + yn.y);
            M = make_float2(yp.x - yn.x, yp.y - yn.y);
        }
        Pa[a][ky] = P;
        Ma[a][ky] = M;
    }
    __syncthreads();

    // Phase A: 1105 items (h=0..64, ky=0..16)
    for (int i = tid; i < 65 * NKY; i += 320) {
        int h = i / NKY, ky = i - h * NKY;
        float C1 = 0.f, C2 = 0.f, S1 = 0.f, S2 = 0.f;
        int p = 0;
        #pragma unroll
        for (int a = 0; a < NKY; a++) {
            float2 t = tb[p & 127];
            float2 P = Pa[a][ky];
            float2 M = Ma[a][ky];
            C1 = fmaf(t.x, P.x, C1);
            C2 = fmaf(t.x, P.y, C2);
            S1 = fmaf(t.y, M.x, S1);
            S2 = fmaf(t.y, M.y, S2);
            p += h;
        }
        Zs[h][ky] = make_float2(C1 - S2, C2 + S1);
        if (h >= 1 && h <= 63)
            Zs[128 - h][ky] = make_float2(C1 + S2, C2 - S1);
    }
    __syncthreads();

    float* op = out + (size_t)blockIdx.x * 16384;

    if (tid < 256) {
        // Phase B main: thread = (w 0..63, h-group of 32)
        const int w  = tid & 63;
        const int h0 = (tid >> 6) * 32;
        float ck[NKY], sk[NKY];
        #pragma unroll
        for (int ky = 0; ky < NKY; ky++) {
            float2 t = tb[(ky * w) & 127];
            float a = ky ? 2.0f : 1.0f;
            ck[ky] = a * t.x;
            sk[ky] = a * t.y;
        }
        for (int h = h0; h < h0 + 32; h++) {
            const float4* zp = (const float4*)(&Zs[h][0]);
            float C = 0.f, S = 0.f;
            #pragma unroll
            for (int j = 0; j < 8; j++) {
                float4 q = zp[j];                 // z[2j], z[2j+1]
                C = fmaf(ck[2 * j],     q.x, C);
                S = fmaf(sk[2 * j],     q.y, S);
                C = fmaf(ck[2 * j + 1], q.z, C);
                S = fmaf(sk[2 * j + 1], q.w, S);
            }
            float2 z16 = Zs[h][16];
            C = fmaf(ck[16], z16.x, C);
            S = fmaf(sk[16], z16.y, S);
            op[h * 128 + w] = C - S;
            if (w) op[h * 128 + 128 - w] = C + S;
        }
    } else {
        // Phase B w=64 column: cos(pi*ky)=(-1)^ky, sin=0. 64 threads x 2 rows.
        int h2 = (tid - 256) * 2;
        #pragma unroll
        for (int r = 0; r < 2; r++) {
            int h = h2 + r;
            float E = 0.f;
            #pragma unroll
            for (int ky = 0; ky < NKY; ky++) {
                float a = ky ? 2.0f : 1.0f;
                float c = (ky & 1) ? -a : a;
                E = fmaf(c, Zs[h][ky].x, E);
            }
            op[h * 128 + 64] = E;
        }
    }
}

extern "C" void kernel_launch(void* const* d_in, const int* in_sizes, int n_in,
                              void* d_out, int out_size) {
    const float* X  = (const float*)d_in[0];
    const float* re = (const float*)d_in[1];
    const float* im = (const float*)d_in[2];
    float* out = (float*)d_out;

    const int smem_fwd = (64 * 18 + 128 * 17 + 128) * 8 + 2 * (128 * 65) * 4; // 94208 B
    cudaFuncSetAttribute(k_fwd, cudaFuncAttributeMaxDynamicSharedMemorySize, smem_fwd);

    k_fwd<<<NSLICE, 320, smem_fwd>>>(X);
    k_mix<<<128, 272>>>(re, im);
    k_inv<<<NSLICE, 320>>>(out);
}